// round 11
// baseline (speedup 1.0000x reference)
#include <cuda_runtime.h>
#include <cstdint>

#define E_    32
#define KK    4
#define H_    1024
#define F_    1024
#define T_    1024
#define TWO_F 2048
#define NSLOT (T_*KK)

// ---------------- scratch (device globals; no allocation) ----------------
__device__ float g_t[T_*H_];
__device__ float g_topk_w[T_*KK];
__device__ int   g_topk_i[T_*KK];
__device__ int   g_cnt[E_];
__device__ int   g_off[E_];
__device__ int   g_tok[NSLOT];
__device__ float g_sw[NSLOT];
__device__ int   g_tslot[T_*KK];
__device__ float g_act[(size_t)NSLOT*F_];
__device__ float g_comb[(size_t)NSLOT*H_];

// ---------------- helpers ----------------
__device__ __forceinline__ uint32_t smem_u32(const void* p) {
    uint32_t a;
    asm("{ .reg .u64 t; cvta.to.shared.u64 t, %1; cvt.u32.u64 %0, t; }" : "=r"(a) : "l"(p));
    return a;
}

#define CPA16(dst, src, sz) \
    asm volatile("cp.async.ca.shared.global [%0], [%1], 16, %2;" \
        :: "r"(dst), "l"(src), "r"(sz))

#define CPA_COMMIT() asm volatile("cp.async.commit_group;")
#define CPA_WAIT1()  asm volatile("cp.async.wait_group 1;")
#define CPA_WAIT0()  asm volatile("cp.async.wait_group 0;")

#define LDMX4(r, addr) \
    asm volatile("ldmatrix.sync.aligned.m8n8.x4.shared.b16 {%0,%1,%2,%3}, [%4];" \
        : "=r"((r)[0]), "=r"((r)[1]), "=r"((r)[2]), "=r"((r)[3]) : "r"(addr))

#define MMA8(d, a, b0, b1) \
    asm volatile("mma.sync.aligned.m16n8k8.row.col.f32.tf32.tf32.f32 " \
        "{%0,%1,%2,%3}, {%4,%5,%6,%7}, {%8,%9}, {%0,%1,%2,%3};" \
        : "+f"((d)[0]), "+f"((d)[1]), "+f"((d)[2]), "+f"((d)[3]) \
        : "r"((a)[0]), "r"((a)[1]), "r"((a)[2]), "r"((a)[3]), "r"(b0), "r"(b1))

// dynamic smem: [0,512) rowtok; stages at 1024: stage s -> A (16KB) + B (16KB)
#define SM_STAGE0  1024
#define STAGE_B    32768
#define SMEM_MLP   (SM_STAGE0 + 3 * STAGE_B)   // 99328 B -> 2 CTAs/SM

// ---------------- kernel 1: fused rmsnorm + gate + top-4 softmax ----------------
__global__ void __launch_bounds__(256) k_norm_gate(
    const float* __restrict__ x, const float* __restrict__ scale,
    const float* __restrict__ gw, const float* __restrict__ gb) {
    __shared__ float ts[H_];
    __shared__ float red[8];
    __shared__ float lg[E_];
    int t = blockIdx.x;
    const float* xr = x + (size_t)t * H_;
    float s = 0.f;
    float xv[4];
    #pragma unroll
    for (int i = 0; i < 4; i++) { xv[i] = xr[threadIdx.x + i * 256]; s += xv[i] * xv[i]; }
    for (int o = 16; o; o >>= 1) s += __shfl_down_sync(0xffffffffu, s, o);
    if ((threadIdx.x & 31) == 0) red[threadIdx.x >> 5] = s;
    __syncthreads();
    if (threadIdx.x < 8) {
        s = red[threadIdx.x];
        for (int o = 4; o; o >>= 1) s += __shfl_down_sync(0xffu, s, o);
        if (threadIdx.x == 0) red[0] = rsqrtf(s / (float)H_ + 1e-5f);
    }
    __syncthreads();
    float r = red[0];
    #pragma unroll
    for (int i = 0; i < 4; i++) {
        int h = threadIdx.x + i * 256;
        float v = xv[i] * r * scale[h];
        ts[h] = v;
        g_t[(size_t)t * H_ + h] = v;
    }
    __syncthreads();
    int e = threadIdx.x >> 3, j = threadIdx.x & 7;
    const float* wr = gw + (size_t)e * H_;
    float acc = 0.f;
    for (int h = j * 4; h < H_; h += 32)
        acc += ts[h]*wr[h] + ts[h+1]*wr[h+1] + ts[h+2]*wr[h+2] + ts[h+3]*wr[h+3];
    for (int o = 4; o; o >>= 1) acc += __shfl_down_sync(0xffffffffu, acc, o);
    if (j == 0) lg[e] = acc + gb[e];
    __syncthreads();
    if (threadIdx.x == 0) {
        float v[E_];
        #pragma unroll
        for (int i = 0; i < E_; i++) v[i] = lg[i];
        float tv[KK]; int ti[KK];
        for (int k = 0; k < KK; k++) {
            float best = -1e30f; int bi = 0;
            for (int i = 0; i < E_; i++) if (v[i] > best) { best = v[i]; bi = i; }
            tv[k] = best; ti[k] = bi; v[bi] = -1e30f;
        }
        float m = tv[0], den = 0.f, ex[KK];
        for (int k = 0; k < KK; k++) { ex[k] = expf(tv[k] - m); den += ex[k]; }
        for (int k = 0; k < KK; k++) {
            g_topk_w[t*KK + k] = ex[k] / den;
            g_topk_i[t*KK + k] = ti[k];
        }
    }
}

// ---------------- kernel 2: parallel deterministic grouping ----------------
__global__ void __launch_bounds__(1024) k_build() {
    __shared__ uint32_t wmask[32][E_];
    __shared__ int scanwe[32][E_];
    __shared__ int cnt_s[E_], off_s[E_];
    int t = threadIdx.x, w = t >> 5, lane = t & 31;

    ((uint32_t*)wmask)[t] = 0u;
    __syncthreads();

    int es[KK]; float ws[KK];
    #pragma unroll
    for (int j = 0; j < KK; j++) {
        es[j] = g_topk_i[t * KK + j];
        ws[j] = g_topk_w[t * KK + j];
        atomicOr(&wmask[w][es[j]], 1u << lane);
    }
    __syncthreads();

    if (t < E_) {
        int run = 0;
        #pragma unroll
        for (int ww = 0; ww < 32; ww++) {
            scanwe[ww][t] = run;
            run += __popc(wmask[ww][t]);
        }
        cnt_s[t] = run;
        g_cnt[t] = run;
    }
    __syncthreads();
    if (t == 0) {
        int r = 0;
        #pragma unroll
        for (int i = 0; i < E_; i++) { off_s[i] = r; g_off[i] = r; r += cnt_s[i]; }
    }
    __syncthreads();

    uint32_t ltmask = (1u << lane) - 1u;
    #pragma unroll
    for (int j = 0; j < KK; j++) {
        int e = es[j];
        int p = off_s[e] + scanwe[w][e] + __popc(wmask[w][e] & ltmask);
        g_tok[p] = t;
        g_sw[p] = ws[j];
        g_tslot[t * KK + j] = p;
    }
}

// =====================================================================
// grouped GEMM: BM=128, BN=128, BK=32, 128 threads (4 warps as 2Mx2N,
// warp tile 64x64 -> 2x B/A fragment reuse), mma.sync m16n8k8 tf32,
// ldmatrix.x4.b16 on XOR-swizzled K-major tiles, 3-stage cp.async,
// 2 CTAs/SM, reg->gmem fused epilogue.
// =====================================================================

__device__ __forceinline__ float swiglu(float glu, float lin) {
    glu = fminf(glu, 7.0f);
    lin = fminf(fmaxf(lin, -7.0f), 7.0f);
    float sig = 1.f / (1.f + __expf(-1.702f * glu));
    return glu * sig * (lin + 1.f);
}

__global__ void __launch_bounds__(128, 2)
k_mlp1(const float* __restrict__ w1, const float* __restrict__ b1) {
    extern __shared__ char smem[];
    int e = blockIdx.z, mtile = blockIdx.y, ntile = blockIdx.x;
    int cnt = g_cnt[e];
    if (mtile * 128 >= cnt) return;
    int off = g_off[e];
    int tid = threadIdx.x, wid = tid >> 5, lane = tid & 31;
    int wm = wid & 1, wn = wid >> 1;
    int grp = lane >> 3, rin = lane & 7;
    uint32_t sb = smem_u32(smem);

    int* rowtok = (int*)smem;
    {
        int m = mtile * 128 + tid;
        rowtok[tid] = (m < cnt) ? g_tok[off + m] : -1;
    }
    __syncthreads();

    const float* Bb = w1 + ((size_t)e * TWO_F + (size_t)ntile * 128) * H_;

    int frow = tid >> 3, fc = tid & 7;                 // 16 rows per i-step
    uint32_t fswz = (uint32_t)((fc ^ (frow & 7)) * 16);

    auto issue = [&](int kt) {
        int s = kt - (kt / 3) * 3;
        int k0 = kt * 32;
        uint32_t Ab = sb + SM_STAGE0 + s * STAGE_B;
        uint32_t Bbuf = Ab + 16384;
        #pragma unroll
        for (int i = 0; i < 8; i++) {
            int row = frow + i * 16;
            int tok = rowtok[row];
            const float* src = g_t + (size_t)(tok < 0 ? 0 : tok) * H_ + k0 + fc * 4;
            int sz = (tok >= 0) ? 16 : 0;
            CPA16(Ab + row * 128 + fswz, src, sz);
        }
        #pragma unroll
        for (int i = 0; i < 8; i++) {
            int row = frow + i * 16;
            const float* src = Bb + (size_t)row * H_ + k0 + fc * 4;
            CPA16(Bbuf + row * 128 + fswz, src, 16);
        }
        CPA_COMMIT();
    };

    float acc[4][8][4];
    #pragma unroll
    for (int mi = 0; mi < 4; mi++)
        #pragma unroll
        for (int ni = 0; ni < 8; ni++)
            #pragma unroll
            for (int q = 0; q < 4; q++) acc[mi][ni][q] = 0.f;

    issue(0); issue(1);

    uint32_t aOff = (uint32_t)((wm * 64 + (grp & 1) * 8 + rin) * 128);
    uint32_t bOff = (uint32_t)((wn * 64 + (grp >> 1) * 8 + rin) * 128);
    int caH = grp >> 1, cbH = grp & 1;

    for (int kt = 0; kt < 32; kt++) {
        int s = kt - (kt / 3) * 3;
        if (kt < 30) { CPA_WAIT1(); } else { CPA_WAIT0(); }
        __syncthreads();
        if (kt + 2 < 32) issue(kt + 2);

        uint32_t Ab = sb + SM_STAGE0 + s * STAGE_B;
        uint32_t Bbuf = Ab + 16384;
        uint32_t aBase = Ab + aOff;
        uint32_t bBase = Bbuf + bOff;

        #pragma unroll
        for (int ks = 0; ks < 4; ks++) {
            uint32_t a[4][4], b[4][4];
            uint32_t ca = (uint32_t)(((2 * ks + caH) ^ rin) * 16);
            uint32_t cb = (uint32_t)(((2 * ks + cbH) ^ rin) * 16);
            #pragma unroll
            for (int mi = 0; mi < 4; mi++) LDMX4(a[mi], aBase + mi * 2048 + ca);
            #pragma unroll
            for (int j = 0; j < 4; j++)  LDMX4(b[j], bBase + j * 2048 + cb);
            #pragma unroll
            for (int mi = 0; mi < 4; mi++)
                #pragma unroll
                for (int j = 0; j < 4; j++) {
                    MMA8(acc[mi][2*j],     a[mi], b[j][0], b[j][1]);
                    MMA8(acc[mi][2*j + 1], a[mi], b[j][2], b[j][3]);
                }
        }
    }

    // fused epilogue: bias + interleaved swiglu, regs -> g_act
    int nv = min(128, cnt - mtile * 128);
    int q = lane & 3, rr = lane >> 2;
    const float* b1p = b1 + (size_t)e * TWO_F + ntile * 128 + wn * 64;
    float be[8], bo[8];
    #pragma unroll
    for (int ni = 0; ni < 8; ni++) {
        be[ni] = __ldg(b1p + ni * 8 + 2 * q);
        bo[ni] = __ldg(b1p + ni * 8 + 2 * q + 1);
    }
    int acol0 = ntile * 64 + wn * 32;
    int mrowbase = off + mtile * 128;
    #pragma unroll
    for (int mi = 0; mi < 4; mi++) {
        int r1 = wm * 64 + mi * 16 + rr;
        #pragma unroll
        for (int ni = 0; ni < 8; ni++) {
            int ac = acol0 + ni * 4 + q;
            if (r1 < nv)
                g_act[(size_t)(mrowbase + r1) * F_ + ac] =
                    swiglu(acc[mi][ni][0] + be[ni], acc[mi][ni][1] + bo[ni]);
            if (r1 + 8 < nv)
                g_act[(size_t)(mrowbase + r1 + 8) * F_ + ac] =
                    swiglu(acc[mi][ni][2] + be[ni], acc[mi][ni][3] + bo[ni]);
        }
    }
}

__global__ void __launch_bounds__(128, 2)
k_mlp2(const float* __restrict__ w2, const float* __restrict__ b2) {
    extern __shared__ char smem[];
    int e = blockIdx.z, mtile = blockIdx.y, ntile = blockIdx.x;
    int cnt = g_cnt[e];
    if (mtile * 128 >= cnt) return;
    int off = g_off[e];
    int tid = threadIdx.x, wid = tid >> 5, lane = tid & 31;
    int wm = wid & 1, wn = wid >> 1;
    int grp = lane >> 3, rin = lane & 7;
    uint32_t sb = smem_u32(smem);

    const float* Bb = w2 + ((size_t)e * H_ + (size_t)ntile * 128) * F_;

    int frow = tid >> 3, fc = tid & 7;
    uint32_t fswz = (uint32_t)((fc ^ (frow & 7)) * 16);

    auto issue = [&](int kt) {
        int s = kt - (kt / 3) * 3;
        int k0 = kt * 32;
        uint32_t Ab = sb + SM_STAGE0 + s * STAGE_B;
        uint32_t Bbuf = Ab + 16384;
        #pragma unroll
        for (int i = 0; i < 8; i++) {
            int row = frow + i * 16;
            int m = mtile * 128 + row;
            int mc = min(m, cnt - 1);
            const float* src = g_act + (size_t)(off + mc) * F_ + k0 + fc * 4;
            int sz = (m < cnt) ? 16 : 0;
            CPA16(Ab + row * 128 + fswz, src, sz);
        }
        #pragma unroll
        for (int i = 0; i < 8; i++) {
            int row = frow + i * 16;
            const float* src = Bb + (size_t)row * F_ + k0 + fc * 4;
            CPA16(Bbuf + row * 128 + fswz, src, 16);
        }
        CPA_COMMIT();
    };

    float acc[4][8][4];
    #pragma unroll
    for (int mi = 0; mi < 4; mi++)
        #pragma unroll
        for (int ni = 0; ni < 8; ni++)
            #pragma unroll
            for (int q = 0; q < 4; q++) acc[mi][ni][q] = 0.f;

    issue(0); issue(1);

    uint32_t aOff = (uint32_t)((wm * 64 + (grp & 1) * 8 + rin) * 128);
    uint32_t bOff = (uint32_t)((wn * 64 + (grp >> 1) * 8 + rin) * 128);
    int caH = grp >> 1, cbH = grp & 1;

    for (int kt = 0; kt < 32; kt++) {
        int s = kt - (kt / 3) * 3;
        if (kt < 30) { CPA_WAIT1(); } else { CPA_WAIT0(); }
        __syncthreads();
        if (kt + 2 < 32) issue(kt + 2);

        uint32_t Ab = sb + SM_STAGE0 + s * STAGE_B;
        uint32_t Bbuf = Ab + 16384;
        uint32_t aBase = Ab + aOff;
        uint32_t bBase = Bbuf + bOff;

        #pragma unroll
        for (int ks = 0; ks < 4; ks++) {
            uint32_t a[4][4], b[4][4];
            uint32_t ca = (uint32_t)(((2 * ks + caH) ^ rin) * 16);
            uint32_t cb = (uint32_t)(((2 * ks + cbH) ^ rin) * 16);
            #pragma unroll
            for (int mi = 0; mi < 4; mi++) LDMX4(a[mi], aBase + mi * 2048 + ca);
            #pragma unroll
            for (int j = 0; j < 4; j++)  LDMX4(b[j], bBase + j * 2048 + cb);
            #pragma unroll
            for (int mi = 0; mi < 4; mi++)
                #pragma unroll
                for (int j = 0; j < 4; j++) {
                    MMA8(acc[mi][2*j],     a[mi], b[j][0], b[j][1]);
                    MMA8(acc[mi][2*j + 1], a[mi], b[j][2], b[j][3]);
                }
        }
    }

    // fused epilogue: (acc + b2) * routing weight -> g_comb
    int nv = min(128, cnt - mtile * 128);
    int q = lane & 3, rr = lane >> 2;
    const float* b2p = b2 + (size_t)e * H_ + ntile * 128 + wn * 64;
    float be[8], bo[8];
    #pragma unroll
    for (int ni = 0; ni < 8; ni++) {
        be[ni] = __ldg(b2p + ni * 8 + 2 * q);
        bo[ni] = __ldg(b2p + ni * 8 + 2 * q + 1);
    }
    int ocol0 = ntile * 128 + wn * 64;
    int slotbase = off + mtile * 128;
    #pragma unroll
    for (int mi = 0; mi < 4; mi++) {
        int r1 = wm * 64 + mi * 16 + rr;
        float sw1 = (r1 < nv)     ? g_sw[slotbase + r1]     : 0.f;
        float sw2 = (r1 + 8 < nv) ? g_sw[slotbase + r1 + 8] : 0.f;
        #pragma unroll
        for (int ni = 0; ni < 8; ni++) {
            int c0 = ni * 8 + 2 * q;
            if (r1 < nv) {
                float2 v = make_float2((acc[mi][ni][0] + be[ni]) * sw1,
                                       (acc[mi][ni][1] + bo[ni]) * sw1);
                *(float2*)&g_comb[(size_t)(slotbase + r1) * H_ + ocol0 + c0] = v;
            }
            if (r1 + 8 < nv) {
                float2 v = make_float2((acc[mi][ni][2] + be[ni]) * sw2,
                                       (acc[mi][ni][3] + bo[ni]) * sw2);
                *(float2*)&g_comb[(size_t)(slotbase + r1 + 8) * H_ + ocol0 + c0] = v;
            }
        }
    }
}

// ---------------- kernel 5: combine + residual ----------------
__global__ void k_combine(const float* __restrict__ x, float* __restrict__ out) {
    int t = blockIdx.x;
    int s0 = g_tslot[t * KK + 0];
    int s1 = g_tslot[t * KK + 1];
    int s2 = g_tslot[t * KK + 2];
    int s3 = g_tslot[t * KK + 3];
    for (int h = threadIdx.x; h < H_; h += 256) {
        out[(size_t)t * H_ + h] = x[(size_t)t * H_ + h]
            + g_comb[(size_t)s0 * H_ + h]
            + g_comb[(size_t)s1 * H_ + h]
            + g_comb[(size_t)s2 * H_ + h]
            + g_comb[(size_t)s3 * H_ + h];
    }
}

// ---------------- launch ----------------
extern "C" void kernel_launch(void* const* d_in, const int* in_sizes, int n_in,
                              void* d_out, int out_size) {
    const float* x  = (const float*)d_in[0];
    const float* ns = (const float*)d_in[1];
    const float* gw = (const float*)d_in[2];
    const float* gb = (const float*)d_in[3];
    const float* w1 = (const float*)d_in[4];
    const float* b1 = (const float*)d_in[5];
    const float* w2 = (const float*)d_in[6];
    const float* b2 = (const float*)d_in[7];
    float* out = (float*)d_out;

    cudaFuncSetAttribute(k_mlp1, cudaFuncAttributeMaxDynamicSharedMemorySize, SMEM_MLP);
    cudaFuncSetAttribute(k_mlp2, cudaFuncAttributeMaxDynamicSharedMemorySize, SMEM_MLP);

    k_norm_gate<<<T_, 256>>>(x, ns, gw, gb);
    k_build<<<1, 1024>>>();
    k_mlp1<<<dim3(16, 8, 32), 128, SMEM_MLP>>>(w1, b1);
    k_mlp2<<<dim3(8, 8, 32), 128, SMEM_MLP>>>(w2, b2);
    k_combine<<<T_, 256>>>(x, out);
}

// round 13
// speedup vs baseline: 1.2397x; 1.2397x over previous
#include <cuda_runtime.h>
#include <cuda_fp16.h>
#include <cstdint>

#define E_    32
#define KK    4
#define H_    1024
#define F_    1024
#define T_    1024
#define TWO_F 2048
#define NSLOT (T_*KK)

// ---------------- scratch (device globals; no allocation) ----------------
__device__ __half g_th[T_*H_];              // fp16 normalized tokens
__device__ float  g_topk_w[T_*KK];
__device__ int    g_topk_i[T_*KK];
__device__ int    g_cnt[E_];
__device__ int    g_off[E_];
__device__ int    g_tok[NSLOT];
__device__ float  g_sw[NSLOT];
__device__ int    g_tslot[T_*KK];
__device__ __half g_act[(size_t)NSLOT*F_];  // fp16 swiglu outputs
__device__ float  g_comb[(size_t)NSLOT*H_];

// ---------------- helpers ----------------
__device__ __forceinline__ uint32_t smem_u32(const void* p) {
    uint32_t a;
    asm("{ .reg .u64 t; cvta.to.shared.u64 t, %1; cvt.u32.u64 %0, t; }" : "=r"(a) : "l"(p));
    return a;
}
__device__ __forceinline__ uint32_t h2_bits(__half2 h) {
    union { __half2 h; uint32_t u; } cvt;
    cvt.h = h;
    return cvt.u;
}

#define CPA16(dst, src, sz) \
    asm volatile("cp.async.ca.shared.global [%0], [%1], 16, %2;" \
        :: "r"(dst), "l"(src), "r"(sz))

#define CPA_COMMIT() asm volatile("cp.async.commit_group;")
#define CPA_WAIT1()  asm volatile("cp.async.wait_group 1;")
#define CPA_WAIT0()  asm volatile("cp.async.wait_group 0;")

#define LDMX4(r, addr) \
    asm volatile("ldmatrix.sync.aligned.m8n8.x4.shared.b16 {%0,%1,%2,%3}, [%4];" \
        : "=r"((r)[0]), "=r"((r)[1]), "=r"((r)[2]), "=r"((r)[3]) : "r"(addr))

#define MMAH(d, a, b0, b1) \
    asm volatile("mma.sync.aligned.m16n8k16.row.col.f32.f16.f16.f32 " \
        "{%0,%1,%2,%3}, {%4,%5,%6,%7}, {%8,%9}, {%0,%1,%2,%3};" \
        : "+f"((d)[0]), "+f"((d)[1]), "+f"((d)[2]), "+f"((d)[3]) \
        : "r"((a)[0]), "r"((a)[1]), "r"((a)[2]), "r"((a)[3]), "r"(b0), "r"(b1))

// dynamic smem: [0,512) rowtok; 3 stages of (A 16KB fp16 + B 16KB fp16)
#define SM_STAGE0  1024
#define STAGE_B    32768
#define SMEM_MLP   (SM_STAGE0 + 3 * STAGE_B)   // 99328 B -> 2 CTAs/SM
#define NK_        16                          // 1024 / BK64

// ---------------- kernel 1: fused rmsnorm + gate + top-4 softmax ----------------
__global__ void __launch_bounds__(256) k_norm_gate(
    const float* __restrict__ x, const float* __restrict__ scale,
    const float* __restrict__ gw, const float* __restrict__ gb) {
    __shared__ float ts[H_];
    __shared__ float red[8];
    __shared__ float lg[E_];
    int t = blockIdx.x;
    const float* xr = x + (size_t)t * H_;
    float s = 0.f;
    float xv[4];
    #pragma unroll
    for (int i = 0; i < 4; i++) { xv[i] = xr[threadIdx.x + i * 256]; s += xv[i] * xv[i]; }
    for (int o = 16; o; o >>= 1) s += __shfl_down_sync(0xffffffffu, s, o);
    if ((threadIdx.x & 31) == 0) red[threadIdx.x >> 5] = s;
    __syncthreads();
    if (threadIdx.x < 8) {
        s = red[threadIdx.x];
        for (int o = 4; o; o >>= 1) s += __shfl_down_sync(0xffu, s, o);
        if (threadIdx.x == 0) red[0] = rsqrtf(s / (float)H_ + 1e-5f);
    }
    __syncthreads();
    float r = red[0];
    #pragma unroll
    for (int i = 0; i < 4; i++) {
        int h = threadIdx.x + i * 256;
        float v = xv[i] * r * scale[h];
        ts[h] = v;
        g_th[(size_t)t * H_ + h] = __float2half_rn(v);
    }
    __syncthreads();
    int e = threadIdx.x >> 3, j = threadIdx.x & 7;
    const float* wr = gw + (size_t)e * H_;
    float acc = 0.f;
    for (int h = j * 4; h < H_; h += 32)
        acc += ts[h]*wr[h] + ts[h+1]*wr[h+1] + ts[h+2]*wr[h+2] + ts[h+3]*wr[h+3];
    for (int o = 4; o; o >>= 1) acc += __shfl_down_sync(0xffffffffu, acc, o);
    if (j == 0) lg[e] = acc + gb[e];
    __syncthreads();
    if (threadIdx.x == 0) {
        float v[E_];
        #pragma unroll
        for (int i = 0; i < E_; i++) v[i] = lg[i];
        float tv[KK]; int ti[KK];
        for (int k = 0; k < KK; k++) {
            float best = -1e30f; int bi = 0;
            for (int i = 0; i < E_; i++) if (v[i] > best) { best = v[i]; bi = i; }
            tv[k] = best; ti[k] = bi; v[bi] = -1e30f;
        }
        float m = tv[0], den = 0.f, ex[KK];
        for (int k = 0; k < KK; k++) { ex[k] = expf(tv[k] - m); den += ex[k]; }
        for (int k = 0; k < KK; k++) {
            g_topk_w[t*KK + k] = ex[k] / den;
            g_topk_i[t*KK + k] = ti[k];
        }
    }
}

// ---------------- kernel 2: parallel deterministic grouping ----------------
__global__ void __launch_bounds__(1024) k_build() {
    __shared__ uint32_t wmask[32][E_];
    __shared__ int scanwe[32][E_];
    __shared__ int cnt_s[E_], off_s[E_];
    int t = threadIdx.x, w = t >> 5, lane = t & 31;

    ((uint32_t*)wmask)[t] = 0u;
    __syncthreads();

    int es[KK]; float ws[KK];
    #pragma unroll
    for (int j = 0; j < KK; j++) {
        es[j] = g_topk_i[t * KK + j];
        ws[j] = g_topk_w[t * KK + j];
        atomicOr(&wmask[w][es[j]], 1u << lane);
    }
    __syncthreads();

    if (t < E_) {
        int run = 0;
        #pragma unroll
        for (int ww = 0; ww < 32; ww++) {
            scanwe[ww][t] = run;
            run += __popc(wmask[ww][t]);
        }
        cnt_s[t] = run;
        g_cnt[t] = run;
    }
    __syncthreads();
    if (t == 0) {
        int r = 0;
        #pragma unroll
        for (int i = 0; i < E_; i++) { off_s[i] = r; g_off[i] = r; r += cnt_s[i]; }
    }
    __syncthreads();

    uint32_t ltmask = (1u << lane) - 1u;
    #pragma unroll
    for (int j = 0; j < KK; j++) {
        int e = es[j];
        int p = off_s[e] + scanwe[w][e] + __popc(wmask[w][e] & ltmask);
        g_tok[p] = t;
        g_sw[p] = ws[j];
        g_tslot[t * KK + j] = p;
    }
}

// =====================================================================
// grouped GEMM: BM=128, BN=128, BK=64 (fp16), mma.sync m16n8k16,
// A fp16 via cp.async, B fp32->fp16 converted in-flight (LDG+cvt+STS),
// XOR-swizzled 128B rows, 3-stage ring, 8 warps as 4Mx2N (32x64 tile),
// 2 CTAs/SM, reg->gmem fused epilogue.
// =====================================================================

__device__ __forceinline__ float swiglu(float glu, float lin) {
    glu = fminf(glu, 7.0f);
    lin = fminf(fmaxf(lin, -7.0f), 7.0f);
    float sig = 1.f / (1.f + __expf(-1.702f * glu));
    return glu * sig * (lin + 1.f);
}

// B fill helpers: thread tid handles one float4 (16B fp32 -> 8B fp16) per row-pass.
// rows: 16 per pass (tid>>4), cols: fc16 = tid&15 -> float4 at fc16*4.
__device__ __forceinline__ void b_ldg4(float4* v, const float* Bb, int kt, int tid, int pbase) {
    int fc16 = tid & 15;
    #pragma unroll
    for (int p = 0; p < 4; p++) {
        int row = (tid >> 4) + (pbase + p) * 16;
        v[p] = *(const float4*)(Bb + (size_t)row * 1024 + kt * 64 + fc16 * 4);
    }
}
__device__ __forceinline__ void b_sts4(const float4* v, char* smem, uint32_t BbufOff, int tid, int pbase) {
    int fc16 = tid & 15;
    int j = fc16 >> 1, sub = fc16 & 1;
    #pragma unroll
    for (int p = 0; p < 4; p++) {
        int row = (tid >> 4) + (pbase + p) * 16;
        uint32_t lo = h2_bits(__floats2half2_rn(v[p].x, v[p].y));
        uint32_t hi = h2_bits(__floats2half2_rn(v[p].z, v[p].w));
        uint32_t off = BbufOff + row * 128 + (uint32_t)((j ^ (row & 7)) * 16) + sub * 8;
        *(uint2*)(smem + off) = make_uint2(lo, hi);
    }
}

__global__ void __launch_bounds__(256, 2)
k_mlp1(const float* __restrict__ w1, const float* __restrict__ b1) {
    extern __shared__ char smem[];
    int e = blockIdx.z, mtile = blockIdx.y, ntile = blockIdx.x;
    int cnt = g_cnt[e];
    if (mtile * 128 >= cnt) return;
    int off = g_off[e];
    int tid = threadIdx.x, wid = tid >> 5, lane = tid & 31;
    int wm = wid & 3, wn = wid >> 2;
    uint32_t sb = smem_u32(smem);

    int* rowtok = (int*)smem;
    if (tid < 128) {
        int m = mtile * 128 + tid;
        rowtok[tid] = (m < cnt) ? g_tok[off + m] : -1;
    }
    __syncthreads();

    const float* Bb = w1 + ((size_t)e * TWO_F + (size_t)ntile * 128) * H_;

    int frow = tid >> 3, fc = tid & 7;
    uint32_t fswz = (uint32_t)((fc ^ (frow & 7)) * 16);

    auto issueA = [&](int kt) {
        int s = kt - (kt / 3) * 3;
        uint32_t Ab = sb + SM_STAGE0 + s * STAGE_B;
        #pragma unroll
        for (int i = 0; i < 4; i++) {
            int row = frow + i * 32;
            int tok = rowtok[row];
            const void* src = (const void*)(g_th + (size_t)(tok < 0 ? 0 : tok) * H_ + kt * 64 + fc * 8);
            int sz = (tok >= 0) ? 16 : 0;
            CPA16(Ab + row * 128 + fswz, src, sz);
        }
        CPA_COMMIT();
    };

    float acc[2][8][4];
    #pragma unroll
    for (int mi = 0; mi < 2; mi++)
        #pragma unroll
        for (int ni = 0; ni < 8; ni++)
            #pragma unroll
            for (int q = 0; q < 4; q++) acc[mi][ni][q] = 0.f;

    issueA(0); issueA(1);
    // B(0) synchronous fill
    {
        float4 v[4];
        b_ldg4(v, Bb, 0, tid, 0); b_sts4(v, smem, SM_STAGE0 + 16384, tid, 0);
        b_ldg4(v, Bb, 0, tid, 4); b_sts4(v, smem, SM_STAGE0 + 16384, tid, 4);
    }

    int rin = lane & 7;
    uint32_t aOff = (uint32_t)((wm * 32 + (lane & 15)) * 128);
    uint32_t bOff = (uint32_t)((wn * 64 + (lane >> 4) * 8 + rin) * 128);
    int caH = lane >> 4;             // A colunit selector
    int cbH = (lane >> 3) & 1;       // B colunit selector

    for (int kt = 0; kt < NK_; kt++) {
        int s = kt - (kt / 3) * 3;
        if (kt < NK_ - 2) { CPA_WAIT1(); } else { CPA_WAIT0(); }
        __syncthreads();
        if (kt + 2 < NK_) issueA(kt + 2);

        uint32_t Ab = sb + SM_STAGE0 + s * STAGE_B;
        uint32_t Bbuf = Ab + 16384;
        uint32_t aBase = Ab + aOff;
        uint32_t bBase = Bbuf + bOff;
        int sn = (kt + 1) - ((kt + 1) / 3) * 3;
        uint32_t BbufN = SM_STAGE0 + sn * STAGE_B + 16384;

        float4 bv[4];
        if (kt + 1 < NK_) b_ldg4(bv, Bb, kt + 1, tid, 0);

        #pragma unroll
        for (int ks = 0; ks < 2; ks++) {
            uint32_t a[2][4], bt[4][4];
            uint32_t ca = (uint32_t)(((2 * ks + caH) ^ rin) * 16);
            uint32_t cb = (uint32_t)(((2 * ks + cbH) ^ rin) * 16);
            LDMX4(a[0], aBase + ca);
            LDMX4(a[1], aBase + 2048 + ca);
            #pragma unroll
            for (int j = 0; j < 4; j++) LDMX4(bt[j], bBase + j * 2048 + cb);
            #pragma unroll
            for (int mi = 0; mi < 2; mi++)
                #pragma unroll
                for (int j = 0; j < 4; j++) {
                    MMAH(acc[mi][2*j],     a[mi], bt[j][0], bt[j][1]);
                    MMAH(acc[mi][2*j + 1], a[mi], bt[j][2], bt[j][3]);
                }
        }
        if (kt + 1 < NK_) { b_sts4(bv, smem, BbufN, tid, 0); b_ldg4(bv, Bb, kt + 1, tid, 4); }
        #pragma unroll
        for (int ks = 2; ks < 4; ks++) {
            uint32_t a[2][4], bt[4][4];
            uint32_t ca = (uint32_t)(((2 * ks + caH) ^ rin) * 16);
            uint32_t cb = (uint32_t)(((2 * ks + cbH) ^ rin) * 16);
            LDMX4(a[0], aBase + ca);
            LDMX4(a[1], aBase + 2048 + ca);
            #pragma unroll
            for (int j = 0; j < 4; j++) LDMX4(bt[j], bBase + j * 2048 + cb);
            #pragma unroll
            for (int mi = 0; mi < 2; mi++)
                #pragma unroll
                for (int j = 0; j < 4; j++) {
                    MMAH(acc[mi][2*j],     a[mi], bt[j][0], bt[j][1]);
                    MMAH(acc[mi][2*j + 1], a[mi], bt[j][2], bt[j][3]);
                }
        }
        if (kt + 1 < NK_) b_sts4(bv, smem, BbufN, tid, 4);
    }

    // fused epilogue: bias + interleaved swiglu -> g_act (fp16)
    int nv = min(128, cnt - mtile * 128);
    int q = lane & 3, rr = lane >> 2;
    const float* b1p = b1 + (size_t)e * TWO_F + ntile * 128 + wn * 64;
    int acol0 = ntile * 64 + wn * 32;
    int mrowbase = off + mtile * 128;
    #pragma unroll
    for (int mi = 0; mi < 2; mi++) {
        int r1 = wm * 32 + mi * 16 + rr;
        #pragma unroll
        for (int ni = 0; ni < 8; ni++) {
            float be = __ldg(b1p + ni * 8 + 2 * q);
            float bo = __ldg(b1p + ni * 8 + 2 * q + 1);
            int ac = acol0 + ni * 4 + q;
            if (r1 < nv)
                g_act[(size_t)(mrowbase + r1) * F_ + ac] =
                    __float2half_rn(swiglu(acc[mi][ni][0] + be, acc[mi][ni][1] + bo));
            if (r1 + 8 < nv)
                g_act[(size_t)(mrowbase + r1 + 8) * F_ + ac] =
                    __float2half_rn(swiglu(acc[mi][ni][2] + be, acc[mi][ni][3] + bo));
        }
    }
}

__global__ void __launch_bounds__(256, 2)
k_mlp2(const float* __restrict__ w2, const float* __restrict__ b2) {
    extern __shared__ char smem[];
    int e = blockIdx.z, mtile = blockIdx.y, ntile = blockIdx.x;
    int cnt = g_cnt[e];
    if (mtile * 128 >= cnt) return;
    int off = g_off[e];
    int tid = threadIdx.x, wid = tid >> 5, lane = tid & 31;
    int wm = wid & 3, wn = wid >> 2;
    uint32_t sb = smem_u32(smem);

    const float* Bb = w2 + ((size_t)e * H_ + (size_t)ntile * 128) * F_;

    int frow = tid >> 3, fc = tid & 7;
    uint32_t fswz = (uint32_t)((fc ^ (frow & 7)) * 16);

    auto issueA = [&](int kt) {
        int s = kt - (kt / 3) * 3;
        uint32_t Ab = sb + SM_STAGE0 + s * STAGE_B;
        #pragma unroll
        for (int i = 0; i < 4; i++) {
            int row = frow + i * 32;
            int m = mtile * 128 + row;
            int mc = min(m, cnt - 1);
            const void* src = (const void*)(g_act + (size_t)(off + mc) * F_ + kt * 64 + fc * 8);
            int sz = (m < cnt) ? 16 : 0;
            CPA16(Ab + row * 128 + fswz, src, sz);
        }
        CPA_COMMIT();
    };

    float acc[2][8][4];
    #pragma unroll
    for (int mi = 0; mi < 2; mi++)
        #pragma unroll
        for (int ni = 0; ni < 8; ni++)
            #pragma unroll
            for (int q = 0; q < 4; q++) acc[mi][ni][q] = 0.f;

    issueA(0); issueA(1);
    {
        float4 v[4];
        b_ldg4(v, Bb, 0, tid, 0); b_sts4(v, smem, SM_STAGE0 + 16384, tid, 0);
        b_ldg4(v, Bb, 0, tid, 4); b_sts4(v, smem, SM_STAGE0 + 16384, tid, 4);
    }

    int rin = lane & 7;
    uint32_t aOff = (uint32_t)((wm * 32 + (lane & 15)) * 128);
    uint32_t bOff = (uint32_t)((wn * 64 + (lane >> 4) * 8 + rin) * 128);
    int caH = lane >> 4;
    int cbH = (lane >> 3) & 1;

    for (int kt = 0; kt < NK_; kt++) {
        int s = kt - (kt / 3) * 3;
        if (kt < NK_ - 2) { CPA_WAIT1(); } else { CPA_WAIT0(); }
        __syncthreads();
        if (kt + 2 < NK_) issueA(kt + 2);

        uint32_t Ab = sb + SM_STAGE0 + s * STAGE_B;
        uint32_t Bbuf = Ab + 16384;
        uint32_t aBase = Ab + aOff;
        uint32_t bBase = Bbuf + bOff;
        int sn = (kt + 1) - ((kt + 1) / 3) * 3;
        uint32_t BbufN = SM_STAGE0 + sn * STAGE_B + 16384;

        float4 bv[4];
        if (kt + 1 < NK_) b_ldg4(bv, Bb, kt + 1, tid, 0);

        #pragma unroll
        for (int ks = 0; ks < 2; ks++) {
            uint32_t a[2][4], bt[4][4];
            uint32_t ca = (uint32_t)(((2 * ks + caH) ^ rin) * 16);
            uint32_t cb = (uint32_t)(((2 * ks + cbH) ^ rin) * 16);
            LDMX4(a[0], aBase + ca);
            LDMX4(a[1], aBase + 2048 + ca);
            #pragma unroll
            for (int j = 0; j < 4; j++) LDMX4(bt[j], bBase + j * 2048 + cb);
            #pragma unroll
            for (int mi = 0; mi < 2; mi++)
                #pragma unroll
                for (int j = 0; j < 4; j++) {
                    MMAH(acc[mi][2*j],     a[mi], bt[j][0], bt[j][1]);
                    MMAH(acc[mi][2*j + 1], a[mi], bt[j][2], bt[j][3]);
                }
        }
        if (kt + 1 < NK_) { b_sts4(bv, smem, BbufN, tid, 0); b_ldg4(bv, Bb, kt + 1, tid, 4); }
        #pragma unroll
        for (int ks = 2; ks < 4; ks++) {
            uint32_t a[2][4], bt[4][4];
            uint32_t ca = (uint32_t)(((2 * ks + caH) ^ rin) * 16);
            uint32_t cb = (uint32_t)(((2 * ks + cbH) ^ rin) * 16);
            LDMX4(a[0], aBase + ca);
            LDMX4(a[1], aBase + 2048 + ca);
            #pragma unroll
            for (int j = 0; j < 4; j++) LDMX4(bt[j], bBase + j * 2048 + cb);
            #pragma unroll
            for (int mi = 0; mi < 2; mi++)
                #pragma unroll
                for (int j = 0; j < 4; j++) {
                    MMAH(acc[mi][2*j],     a[mi], bt[j][0], bt[j][1]);
                    MMAH(acc[mi][2*j + 1], a[mi], bt[j][2], bt[j][3]);
                }
        }
        if (kt + 1 < NK_) b_sts4(bv, smem, BbufN, tid, 4);
    }

    // fused epilogue: (acc + b2) * routing weight -> g_comb (fp32)
    int nv = min(128, cnt - mtile * 128);
    int q = lane & 3, rr = lane >> 2;
    const float* b2p = b2 + (size_t)e * H_ + ntile * 128 + wn * 64;
    int ocol0 = ntile * 128 + wn * 64;
    int slotbase = off + mtile * 128;
    #pragma unroll
    for (int mi = 0; mi < 2; mi++) {
        int r1 = wm * 32 + mi * 16 + rr;
        float sw1 = (r1 < nv)     ? g_sw[slotbase + r1]     : 0.f;
        float sw2 = (r1 + 8 < nv) ? g_sw[slotbase + r1 + 8] : 0.f;
        #pragma unroll
        for (int ni = 0; ni < 8; ni++) {
            int c0 = ni * 8 + 2 * q;
            float be = __ldg(b2p + c0);
            float bo = __ldg(b2p + c0 + 1);
            if (r1 < nv) {
                float2 v = make_float2((acc[mi][ni][0] + be) * sw1,
                                       (acc[mi][ni][1] + bo) * sw1);
                *(float2*)&g_comb[(size_t)(slotbase + r1) * H_ + ocol0 + c0] = v;
            }
            if (r1 + 8 < nv) {
                float2 v = make_float2((acc[mi][ni][2] + be) * sw2,
                                       (acc[mi][ni][3] + bo) * sw2);
                *(float2*)&g_comb[(size_t)(slotbase + r1 + 8) * H_ + ocol0 + c0] = v;
            }
        }
    }
}

// ---------------- kernel 5: combine + residual ----------------
__global__ void k_combine(const float* __restrict__ x, float* __restrict__ out) {
    int t = blockIdx.x;
    int s0 = g_tslot[t * KK + 0];
    int s1 = g_tslot[t * KK + 1];
    int s2 = g_tslot[t * KK + 2];
    int s3 = g_tslot[t * KK + 3];
    for (int h = threadIdx.x; h < H_; h += 256) {
        out[(size_t)t * H_ + h] = x[(size_t)t * H_ + h]
            + g_comb[(size_t)s0 * H_ + h]
            + g_comb[(size_t)s1 * H_ + h]
            + g_comb[(size_t)s2 * H_ + h]
            + g_comb[(size_t)s3 * H_ + h];
    }
}

// ---------------- launch ----------------
extern "C" void kernel_launch(void* const* d_in, const int* in_sizes, int n_in,
                              void* d_out, int out_size) {
    const float* x  = (const float*)d_in[0];
    const float* ns = (const float*)d_in[1];
    const float* gw = (const float*)d_in[2];
    const float* gb = (const float*)d_in[3];
    const float* w1 = (const float*)d_in[4];
    const float* b1 = (const float*)d_in[5];
    const float* w2 = (const float*)d_in[6];
    const float* b2 = (const float*)d_in[7];
    float* out = (float*)d_out;

    cudaFuncSetAttribute(k_mlp1, cudaFuncAttributeMaxDynamicSharedMemorySize, SMEM_MLP);
    cudaFuncSetAttribute(k_mlp2, cudaFuncAttributeMaxDynamicSharedMemorySize, SMEM_MLP);

    k_norm_gate<<<T_, 256>>>(x, ns, gw, gb);
    k_build<<<1, 1024>>>();
    k_mlp1<<<dim3(16, 8, 32), 256, SMEM_MLP>>>(w1, b1);
    k_mlp2<<<dim3(8, 8, 32), 256, SMEM_MLP>>>(w2, b2);
    k_combine<<<T_, 256>>>(x, out);
}

// round 16
// speedup vs baseline: 1.3203x; 1.0650x over previous
#include <cuda_runtime.h>
#include <cuda_fp16.h>
#include <cstdint>

#define E_    32
#define KK    4
#define H_    1024
#define F_    1024
#define T_    1024
#define TWO_F 2048
#define NSLOT (T_*KK)

// ---------------- scratch (device globals; no allocation) ----------------
__device__ __half g_th[T_*H_];              // fp16 normalized tokens
__device__ float  g_topk_w[T_*KK];
__device__ int    g_topk_i[T_*KK];
__device__ int    g_cnt[E_];
__device__ int    g_off[E_];
__device__ int    g_tok[NSLOT];
__device__ float  g_sw[NSLOT];
__device__ int    g_tslot[T_*KK];
__device__ __half g_act[(size_t)NSLOT*F_];  // fp16 swiglu outputs
__device__ float  g_comb[(size_t)NSLOT*H_];

// ---------------- helpers ----------------
__device__ __forceinline__ uint32_t smem_u32(const void* p) {
    uint32_t a;
    asm("{ .reg .u64 t; cvta.to.shared.u64 t, %1; cvt.u32.u64 %0, t; }" : "=r"(a) : "l"(p));
    return a;
}
__device__ __forceinline__ uint32_t h2_bits(__half2 h) {
    union { __half2 h; uint32_t u; } cvt;
    cvt.h = h;
    return cvt.u;
}
__device__ __forceinline__ void l2_prefetch(const void* p) {
    asm volatile("prefetch.global.L2 [%0];" :: "l"(p));
}

#define CPA16(dst, src, sz) \
    asm volatile("cp.async.ca.shared.global [%0], [%1], 16, %2;" \
        :: "r"(dst), "l"(src), "r"(sz))

#define CPA_COMMIT() asm volatile("cp.async.commit_group;")
#define CPA_WAIT1()  asm volatile("cp.async.wait_group 1;")
#define CPA_WAIT0()  asm volatile("cp.async.wait_group 0;")

#define LDMX4(r, addr) \
    asm volatile("ldmatrix.sync.aligned.m8n8.x4.shared.b16 {%0,%1,%2,%3}, [%4];" \
        : "=r"((r)[0]), "=r"((r)[1]), "=r"((r)[2]), "=r"((r)[3]) : "r"(addr))

#define MMAH(d, a, b0, b1) \
    asm volatile("mma.sync.aligned.m16n8k16.row.col.f32.f16.f16.f32 " \
        "{%0,%1,%2,%3}, {%4,%5,%6,%7}, {%8,%9}, {%0,%1,%2,%3};" \
        : "+f"((d)[0]), "+f"((d)[1]), "+f"((d)[2]), "+f"((d)[3]) \
        : "r"((a)[0]), "r"((a)[1]), "r"((a)[2]), "r"((a)[3]), "r"(b0), "r"(b1))

// dynamic smem: [0,512) rowtok; 3 stages of (A 16KB fp16 + B 16KB fp16)
#define SM_STAGE0  1024
#define STAGE_B    32768
#define SMEM_MLP   (SM_STAGE0 + 3 * STAGE_B)   // 99328 B -> 2 CTAs/SM
#define NK_        16                          // 1024 / BK64

// ---------------- kernel 1: fused rmsnorm + gate + top-4 softmax ----------------
__global__ void __launch_bounds__(256) k_norm_gate(
    const float* __restrict__ x, const float* __restrict__ scale,
    const float* __restrict__ gw, const float* __restrict__ gb) {
    __shared__ float ts[H_];
    __shared__ float red[8];
    __shared__ float lg[E_];
    int t = blockIdx.x;
    const float* xr = x + (size_t)t * H_;
    float s = 0.f;
    float xv[4];
    #pragma unroll
    for (int i = 0; i < 4; i++) { xv[i] = xr[threadIdx.x + i * 256]; s += xv[i] * xv[i]; }
    for (int o = 16; o; o >>= 1) s += __shfl_down_sync(0xffffffffu, s, o);
    if ((threadIdx.x & 31) == 0) red[threadIdx.x >> 5] = s;
    __syncthreads();
    if (threadIdx.x < 8) {
        s = red[threadIdx.x];
        for (int o = 4; o; o >>= 1) s += __shfl_down_sync(0xffu, s, o);
        if (threadIdx.x == 0) red[0] = rsqrtf(s / (float)H_ + 1e-5f);
    }
    __syncthreads();
    float r = red[0];
    #pragma unroll
    for (int i = 0; i < 4; i++) {
        int h = threadIdx.x + i * 256;
        float v = xv[i] * r * scale[h];
        ts[h] = v;
        g_th[(size_t)t * H_ + h] = __float2half_rn(v);
    }
    __syncthreads();
    int e = threadIdx.x >> 3, j = threadIdx.x & 7;
    const float* wr = gw + (size_t)e * H_;
    float acc = 0.f;
    for (int h = j * 4; h < H_; h += 32)
        acc += ts[h]*wr[h] + ts[h+1]*wr[h+1] + ts[h+2]*wr[h+2] + ts[h+3]*wr[h+3];
    for (int o = 4; o; o >>= 1) acc += __shfl_down_sync(0xffffffffu, acc, o);
    if (j == 0) lg[e] = acc + gb[e];
    __syncthreads();
    if (threadIdx.x == 0) {
        float v[E_];
        #pragma unroll
        for (int i = 0; i < E_; i++) v[i] = lg[i];
        float tv[KK]; int ti[KK];
        for (int k = 0; k < KK; k++) {
            float best = -1e30f; int bi = 0;
            for (int i = 0; i < E_; i++) if (v[i] > best) { best = v[i]; bi = i; }
            tv[k] = best; ti[k] = bi; v[bi] = -1e30f;
        }
        float m = tv[0], den = 0.f, ex[KK];
        for (int k = 0; k < KK; k++) { ex[k] = expf(tv[k] - m); den += ex[k]; }
        for (int k = 0; k < KK; k++) {
            g_topk_w[t*KK + k] = ex[k] / den;
            g_topk_i[t*KK + k] = ti[k];
        }
    }
}

// ---------------- kernel 2: parallel deterministic grouping ----------------
__global__ void __launch_bounds__(1024) k_build() {
    __shared__ uint32_t wmask[32][E_];
    __shared__ int scanwe[32][E_];
    __shared__ int cnt_s[E_], off_s[E_];
    int t = threadIdx.x, w = t >> 5, lane = t & 31;

    ((uint32_t*)wmask)[t] = 0u;
    __syncthreads();

    int es[KK]; float ws[KK];
    #pragma unroll
    for (int j = 0; j < KK; j++) {
        es[j] = g_topk_i[t * KK + j];
        ws[j] = g_topk_w[t * KK + j];
        atomicOr(&wmask[w][es[j]], 1u << lane);
    }
    __syncthreads();

    if (t < E_) {
        int run = 0;
        #pragma unroll
        for (int ww = 0; ww < 32; ww++) {
            scanwe[ww][t] = run;
            run += __popc(wmask[ww][t]);
        }
        cnt_s[t] = run;
        g_cnt[t] = run;
    }
    __syncthreads();
    if (t == 0) {
        int r = 0;
        #pragma unroll
        for (int i = 0; i < E_; i++) { off_s[i] = r; g_off[i] = r; r += cnt_s[i]; }
    }
    __syncthreads();

    uint32_t ltmask = (1u << lane) - 1u;
    #pragma unroll
    for (int j = 0; j < KK; j++) {
        int e = es[j];
        int p = off_s[e] + scanwe[w][e] + __popc(wmask[w][e] & ltmask);
        g_tok[p] = t;
        g_sw[p] = ws[j];
        g_tslot[t * KK + j] = p;
    }
}

// =====================================================================
// grouped GEMM: BM=128, BN=128, BK=64 (fp16), mma.sync m16n8k16,
// A fp16 via cp.async, B fp32->fp16 converted in-flight (LDG+cvt+STS)
// with L2 prefetch 2 k-tiles ahead, XOR-swizzled 128B rows, 3-stage
// ring, 8 warps as 4Mx2N (32x64 tile), 2 CTAs/SM, reg->gmem epilogue.
// =====================================================================

__device__ __forceinline__ float swiglu(float glu, float lin) {
    glu = fminf(glu, 7.0f);
    lin = fminf(fmaxf(lin, -7.0f), 7.0f);
    float sig = 1.f / (1.f + __expf(-1.702f * glu));
    return glu * sig * (lin + 1.f);
}

// B fill helpers: thread tid handles one float4 (16B fp32 -> 8B fp16) per row-pass.
__device__ __forceinline__ void b_ldg4(float4* v, const float* Bb, int kt, int tid, int pbase) {
    int fc16 = tid & 15;
    #pragma unroll
    for (int p = 0; p < 4; p++) {
        int row = (tid >> 4) + (pbase + p) * 16;
        v[p] = *(const float4*)(Bb + (size_t)row * 1024 + kt * 64 + fc16 * 4);
    }
}
__device__ __forceinline__ void b_sts4(const float4* v, char* smem, uint32_t BbufOff, int tid, int pbase) {
    int fc16 = tid & 15;
    int j = fc16 >> 1, sub = fc16 & 1;
    #pragma unroll
    for (int p = 0; p < 4; p++) {
        int row = (tid >> 4) + (pbase + p) * 16;
        uint32_t lo = h2_bits(__floats2half2_rn(v[p].x, v[p].y));
        uint32_t hi = h2_bits(__floats2half2_rn(v[p].z, v[p].w));
        uint32_t off = BbufOff + row * 128 + (uint32_t)((j ^ (row & 7)) * 16) + sub * 8;
        *(uint2*)(smem + off) = make_uint2(lo, hi);
    }
}
// L2 prefetch for the FULL B k-tile (128 rows x 64 fp32 = 2 lines/row).
// One thread per 128B line: fc16 in {0, 8}.
__device__ __forceinline__ void b_pref(const float* Bb, int kt, int tid) {
    int fc16 = tid & 15;
    if ((fc16 & 7) == 0) {
        #pragma unroll
        for (int p = 0; p < 8; p++) {
            int row = (tid >> 4) + p * 16;
            l2_prefetch(Bb + (size_t)row * 1024 + kt * 64 + fc16 * 4);
        }
    }
}

__global__ void __launch_bounds__(256, 2)
k_mlp1(const float* __restrict__ w1, const float* __restrict__ b1) {
    extern __shared__ char smem[];
    int e = blockIdx.z, mtile = blockIdx.y, ntile = blockIdx.x;
    int cnt = g_cnt[e];
    if (mtile * 128 >= cnt) return;
    int off = g_off[e];
    int tid = threadIdx.x, wid = tid >> 5, lane = tid & 31;
    int wm = wid & 3, wn = wid >> 2;
    uint32_t sb = smem_u32(smem);

    int* rowtok = (int*)smem;
    if (tid < 128) {
        int m = mtile * 128 + tid;
        rowtok[tid] = (m < cnt) ? g_tok[off + m] : -1;
    }
    __syncthreads();

    const float* Bb = w1 + ((size_t)e * TWO_F + (size_t)ntile * 128) * H_;

    int frow = tid >> 3, fc = tid & 7;
    uint32_t fswz = (uint32_t)((fc ^ (frow & 7)) * 16);

    auto issueA = [&](int kt) {
        int s = kt - (kt / 3) * 3;
        uint32_t Ab = sb + SM_STAGE0 + s * STAGE_B;
        #pragma unroll
        for (int i = 0; i < 4; i++) {
            int row = frow + i * 32;
            int tok = rowtok[row];
            const void* src = (const void*)(g_th + (size_t)(tok < 0 ? 0 : tok) * H_ + kt * 64 + fc * 8);
            int sz = (tok >= 0) ? 16 : 0;
            CPA16(Ab + row * 128 + fswz, src, sz);
        }
        CPA_COMMIT();
    };

    float acc[2][8][4];
    #pragma unroll
    for (int mi = 0; mi < 2; mi++)
        #pragma unroll
        for (int ni = 0; ni < 8; ni++)
            #pragma unroll
            for (int q = 0; q < 4; q++) acc[mi][ni][q] = 0.f;

    issueA(0); issueA(1);
    b_pref(Bb, 1, tid);
    // B(0) synchronous fill
    {
        float4 v[4];
        b_ldg4(v, Bb, 0, tid, 0); b_sts4(v, smem, SM_STAGE0 + 16384, tid, 0);
        b_ldg4(v, Bb, 0, tid, 4); b_sts4(v, smem, SM_STAGE0 + 16384, tid, 4);
    }

    int rin = lane & 7;
    uint32_t aOff = (uint32_t)((wm * 32 + (lane & 15)) * 128);
    uint32_t bOff = (uint32_t)((wn * 64 + (lane >> 4) * 8 + rin) * 128);
    int caH = lane >> 4;             // A colunit selector
    int cbH = (lane >> 3) & 1;       // B colunit selector

    for (int kt = 0; kt < NK_; kt++) {
        int s = kt - (kt / 3) * 3;
        if (kt < NK_ - 2) { CPA_WAIT1(); } else { CPA_WAIT0(); }
        __syncthreads();
        if (kt + 2 < NK_) { issueA(kt + 2); b_pref(Bb, kt + 2, tid); }

        uint32_t Ab = sb + SM_STAGE0 + s * STAGE_B;
        uint32_t Bbuf = Ab + 16384;
        uint32_t aBase = Ab + aOff;
        uint32_t bBase = Bbuf + bOff;
        int sn = (kt + 1) - ((kt + 1) / 3) * 3;
        uint32_t BbufN = SM_STAGE0 + sn * STAGE_B + 16384;

        float4 bv[4];
        if (kt + 1 < NK_) b_ldg4(bv, Bb, kt + 1, tid, 0);

        #pragma unroll
        for (int ks = 0; ks < 2; ks++) {
            uint32_t a[2][4], bt[4][4];
            uint32_t ca = (uint32_t)(((2 * ks + caH) ^ rin) * 16);
            uint32_t cb = (uint32_t)(((2 * ks + cbH) ^ rin) * 16);
            LDMX4(a[0], aBase + ca);
            LDMX4(a[1], aBase + 2048 + ca);
            #pragma unroll
            for (int j = 0; j < 4; j++) LDMX4(bt[j], bBase + j * 2048 + cb);
            #pragma unroll
            for (int mi = 0; mi < 2; mi++)
                #pragma unroll
                for (int j = 0; j < 4; j++) {
                    MMAH(acc[mi][2*j],     a[mi], bt[j][0], bt[j][1]);
                    MMAH(acc[mi][2*j + 1], a[mi], bt[j][2], bt[j][3]);
                }
        }
        if (kt + 1 < NK_) { b_sts4(bv, smem, BbufN, tid, 0); b_ldg4(bv, Bb, kt + 1, tid, 4); }
        #pragma unroll
        for (int ks = 2; ks < 4; ks++) {
            uint32_t a[2][4], bt[4][4];
            uint32_t ca = (uint32_t)(((2 * ks + caH) ^ rin) * 16);
            uint32_t cb = (uint32_t)(((2 * ks + cbH) ^ rin) * 16);
            LDMX4(a[0], aBase + ca);
            LDMX4(a[1], aBase + 2048 + ca);
            #pragma unroll
            for (int j = 0; j < 4; j++) LDMX4(bt[j], bBase + j * 2048 + cb);
            #pragma unroll
            for (int mi = 0; mi < 2; mi++)
                #pragma unroll
                for (int j = 0; j < 4; j++) {
                    MMAH(acc[mi][2*j],     a[mi], bt[j][0], bt[j][1]);
                    MMAH(acc[mi][2*j + 1], a[mi], bt[j][2], bt[j][3]);
                }
        }
        if (kt + 1 < NK_) b_sts4(bv, smem, BbufN, tid, 4);
    }

    // fused epilogue: bias + interleaved swiglu -> g_act (fp16)
    int nv = min(128, cnt - mtile * 128);
    int q = lane & 3, rr = lane >> 2;
    const float* b1p = b1 + (size_t)e * TWO_F + ntile * 128 + wn * 64;
    int acol0 = ntile * 64 + wn * 32;
    int mrowbase = off + mtile * 128;
    #pragma unroll
    for (int mi = 0; mi < 2; mi++) {
        int r1 = wm * 32 + mi * 16 + rr;
        #pragma unroll
        for (int ni = 0; ni < 8; ni++) {
            float be = __ldg(b1p + ni * 8 + 2 * q);
            float bo = __ldg(b1p + ni * 8 + 2 * q + 1);
            int ac = acol0 + ni * 4 + q;
            if (r1 < nv)
                g_act[(size_t)(mrowbase + r1) * F_ + ac] =
                    __float2half_rn(swiglu(acc[mi][ni][0] + be, acc[mi][ni][1] + bo));
            if (r1 + 8 < nv)
                g_act[(size_t)(mrowbase + r1 + 8) * F_ + ac] =
                    __float2half_rn(swiglu(acc[mi][ni][2] + be, acc[mi][ni][3] + bo));
        }
    }
}

__global__ void __launch_bounds__(256, 2)
k_mlp2(const float* __restrict__ w2, const float* __restrict__ b2) {
    extern __shared__ char smem[];
    int e = blockIdx.z, mtile = blockIdx.y, ntile = blockIdx.x;
    int cnt = g_cnt[e];
    if (mtile * 128 >= cnt) return;
    int off = g_off[e];
    int tid = threadIdx.x, wid = tid >> 5, lane = tid & 31;
    int wm = wid & 3, wn = wid >> 2;
    uint32_t sb = smem_u32(smem);

    const float* Bb = w2 + ((size_t)e * H_ + (size_t)ntile * 128) * F_;

    int frow = tid >> 3, fc = tid & 7;
    uint32_t fswz = (uint32_t)((fc ^ (frow & 7)) * 16);

    auto issueA = [&](int kt) {
        int s = kt - (kt / 3) * 3;
        uint32_t Ab = sb + SM_STAGE0 + s * STAGE_B;
        #pragma unroll
        for (int i = 0; i < 4; i++) {
            int row = frow + i * 32;
            int m = mtile * 128 + row;
            int mc = min(m, cnt - 1);
            const void* src = (const void*)(g_act + (size_t)(off + mc) * F_ + kt * 64 + fc * 8);
            int sz = (m < cnt) ? 16 : 0;
            CPA16(Ab + row * 128 + fswz, src, sz);
        }
        CPA_COMMIT();
    };

    float acc[2][8][4];
    #pragma unroll
    for (int mi = 0; mi < 2; mi++)
        #pragma unroll
        for (int ni = 0; ni < 8; ni++)
            #pragma unroll
            for (int q = 0; q < 4; q++) acc[mi][ni][q] = 0.f;

    issueA(0); issueA(1);
    b_pref(Bb, 1, tid);
    {
        float4 v[4];
        b_ldg4(v, Bb, 0, tid, 0); b_sts4(v, smem, SM_STAGE0 + 16384, tid, 0);
        b_ldg4(v, Bb, 0, tid, 4); b_sts4(v, smem, SM_STAGE0 + 16384, tid, 4);
    }

    int rin = lane & 7;
    uint32_t aOff = (uint32_t)((wm * 32 + (lane & 15)) * 128);
    uint32_t bOff = (uint32_t)((wn * 64 + (lane >> 4) * 8 + rin) * 128);
    int caH = lane >> 4;
    int cbH = (lane >> 3) & 1;

    for (int kt = 0; kt < NK_; kt++) {
        int s = kt - (kt / 3) * 3;
        if (kt < NK_ - 2) { CPA_WAIT1(); } else { CPA_WAIT0(); }
        __syncthreads();
        if (kt + 2 < NK_) { issueA(kt + 2); b_pref(Bb, kt + 2, tid); }

        uint32_t Ab = sb + SM_STAGE0 + s * STAGE_B;
        uint32_t Bbuf = Ab + 16384;
        uint32_t aBase = Ab + aOff;
        uint32_t bBase = Bbuf + bOff;
        int sn = (kt + 1) - ((kt + 1) / 3) * 3;
        uint32_t BbufN = SM_STAGE0 + sn * STAGE_B + 16384;

        float4 bv[4];
        if (kt + 1 < NK_) b_ldg4(bv, Bb, kt + 1, tid, 0);

        #pragma unroll
        for (int ks = 0; ks < 2; ks++) {
            uint32_t a[2][4], bt[4][4];
            uint32_t ca = (uint32_t)(((2 * ks + caH) ^ rin) * 16);
            uint32_t cb = (uint32_t)(((2 * ks + cbH) ^ rin) * 16);
            LDMX4(a[0], aBase + ca);
            LDMX4(a[1], aBase + 2048 + ca);
            #pragma unroll
            for (int j = 0; j < 4; j++) LDMX4(bt[j], bBase + j * 2048 + cb);
            #pragma unroll
            for (int mi = 0; mi < 2; mi++)
                #pragma unroll
                for (int j = 0; j < 4; j++) {
                    MMAH(acc[mi][2*j],     a[mi], bt[j][0], bt[j][1]);
                    MMAH(acc[mi][2*j + 1], a[mi], bt[j][2], bt[j][3]);
                }
        }
        if (kt + 1 < NK_) { b_sts4(bv, smem, BbufN, tid, 0); b_ldg4(bv, Bb, kt + 1, tid, 4); }
        #pragma unroll
        for (int ks = 2; ks < 4; ks++) {
            uint32_t a[2][4], bt[4][4];
            uint32_t ca = (uint32_t)(((2 * ks + caH) ^ rin) * 16);
            uint32_t cb = (uint32_t)(((2 * ks + cbH) ^ rin) * 16);
            LDMX4(a[0], aBase + ca);
            LDMX4(a[1], aBase + 2048 + ca);
            #pragma unroll
            for (int j = 0; j < 4; j++) LDMX4(bt[j], bBase + j * 2048 + cb);
            #pragma unroll
            for (int mi = 0; mi < 2; mi++)
                #pragma unroll
                for (int j = 0; j < 4; j++) {
                    MMAH(acc[mi][2*j],     a[mi], bt[j][0], bt[j][1]);
                    MMAH(acc[mi][2*j + 1], a[mi], bt[j][2], bt[j][3]);
                }
        }
        if (kt + 1 < NK_) b_sts4(bv, smem, BbufN, tid, 4);
    }

    // fused epilogue: (acc + b2) * routing weight -> g_comb (fp32)
    int nv = min(128, cnt - mtile * 128);
    int q = lane & 3, rr = lane >> 2;
    const float* b2p = b2 + (size_t)e * H_ + ntile * 128 + wn * 64;
    int ocol0 = ntile * 128 + wn * 64;
    int slotbase = off + mtile * 128;
    #pragma unroll
    for (int mi = 0; mi < 2; mi++) {
        int r1 = wm * 32 + mi * 16 + rr;
        float sw1 = (r1 < nv)     ? g_sw[slotbase + r1]     : 0.f;
        float sw2 = (r1 + 8 < nv) ? g_sw[slotbase + r1 + 8] : 0.f;
        #pragma unroll
        for (int ni = 0; ni < 8; ni++) {
            int c0 = ni * 8 + 2 * q;
            float be = __ldg(b2p + c0);
            float bo = __ldg(b2p + c0 + 1);
            if (r1 < nv) {
                float2 v = make_float2((acc[mi][ni][0] + be) * sw1,
                                       (acc[mi][ni][1] + bo) * sw1);
                *(float2*)&g_comb[(size_t)(slotbase + r1) * H_ + ocol0 + c0] = v;
            }
            if (r1 + 8 < nv) {
                float2 v = make_float2((acc[mi][ni][2] + be) * sw2,
                                       (acc[mi][ni][3] + bo) * sw2);
                *(float2*)&g_comb[(size_t)(slotbase + r1 + 8) * H_ + ocol0 + c0] = v;
            }
        }
    }
}

// ---------------- kernel 5: combine + residual ----------------
__global__ void k_combine(const float* __restrict__ x, float* __restrict__ out) {
    int t = blockIdx.x;
    int s0 = g_tslot[t * KK + 0];
    int s1 = g_tslot[t * KK + 1];
    int s2 = g_tslot[t * KK + 2];
    int s3 = g_tslot[t * KK + 3];
    for (int h = threadIdx.x; h < H_; h += 256) {
        out[(size_t)t * H_ + h] = x[(size_t)t * H_ + h]
            + g_comb[(size_t)s0 * H_ + h]
            + g_comb[(size_t)s1 * H_ + h]
            + g_comb[(size_t)s2 * H_ + h]
            + g_comb[(size_t)s3 * H_ + h];
    }
}

// ---------------- launch ----------------
extern "C" void kernel_launch(void* const* d_in, const int* in_sizes, int n_in,
                              void* d_out, int out_size) {
    const float* x  = (const float*)d_in[0];
    const float* ns = (const float*)d_in[1];
    const float* gw = (const float*)d_in[2];
    const float* gb = (const float*)d_in[3];
    const float* w1 = (const float*)d_in[4];
    const float* b1 = (const float*)d_in[5];
    const float* w2 = (const float*)d_in[6];
    const float* b2 = (const float*)d_in[7];
    float* out = (float*)d_out;

    cudaFuncSetAttribute(k_mlp1, cudaFuncAttributeMaxDynamicSharedMemorySize, SMEM_MLP);
    cudaFuncSetAttribute(k_mlp2, cudaFuncAttributeMaxDynamicSharedMemorySize, SMEM_MLP);

    k_norm_gate<<<T_, 256>>>(x, ns, gw, gb);
    k_build<<<1, 1024>>>();
    k_mlp1<<<dim3(16, 8, 32), 256, SMEM_MLP>>>(w1, b1);
    k_mlp2<<<dim3(8, 8, 32), 256, SMEM_MLP>>>(w2, b2);
    k_combine<<<T_, 256>>>(x, out);
}